// round 15
// baseline (speedup 1.0000x reference)
#include <cuda_runtime.h>
#include <cuda_fp16.h>
#include <cstdint>

#define NN   100000   // nodes
#define CF   128      // feature dim (C_in == H == 128)
#define NE   1600000  // edges
#define NS   4096     // subgraphs
#define NL   64       // max subgraph size
#define NCLS 10
#define CAP  96       // per-node bucket capacity (deg ~ Poisson(16); P(>96)~1e-40)

// ---------------- scratch (no allocations allowed -> __device__ globals) ---
__device__ int    g_cur[NN];        // bucket cursors (zero at load; reset in k_pool)
__device__ float  g_dinv[NN];
__device__ int    g_bkt[NN * CAP];  // per-node buckets: BYTE offsets (src*256)
__device__ __half g_hw[NN * CF];    // h @ W scratch (fp16), pre-scaled by dinv[row]
__device__ __half g_h1h[NN * CF];   // layer-1 output (fp16)
__device__ __half g_h2h[NN * CF];   // layer-2 output (fp16)

// ---------------- dtype detection helpers (per-block, no global state) -----
__device__ __forceinline__ int detect_e64(const unsigned int* ei) {
    for (int i = 0; i < 64; i++)
        if (ei[2 * i + 1] != 0u) return 0;
    return 1;
}
__device__ __forceinline__ int detect_s64(const unsigned int* sg) {
    for (int i = 0; i < 64; i++) {
        unsigned hi = sg[2 * i + 1];
        if (hi != 0u && hi != 0xFFFFFFFFu) return 0;
    }
    return 1;
}
__device__ __forceinline__ int load_idx(const void* p, int i, int is64) {
    return is64 ? (int)((const long long*)p)[i] : ((const int*)p)[i];
}
__device__ __forceinline__ int2 load_pair(const void* p, int base, int i, int is64) {
    if (is64) {
        longlong2 v = ((const longlong2*)((const long long*)p + base))[i];
        return make_int2((int)v.x, (int)v.y);
    }
    return ((const int2*)((const int*)p + base))[i];
}

// ---------------- bucket fill (stores byte offsets src*256) ----------------
__global__ void k_fill(const void* __restrict__ ei) {
    __shared__ int s_e64;
    if (threadIdx.x == 0) s_e64 = detect_e64((const unsigned int*)ei);
    __syncthreads();
    int i = blockIdx.x * blockDim.x + threadIdx.x;
    if (i >= NE / 2) return;
    int2 s = load_pair(ei, 0, i, s_e64);
    int2 d = load_pair(ei, NE, i, s_e64);
    int p0 = atomicAdd(&g_cur[d.x], 1);
    int p1 = atomicAdd(&g_cur[d.y], 1);
    if (p0 < CAP) g_bkt[d.x * CAP + p0] = s.x << 8;   // *CF*sizeof(half)=256
    if (p1 < CAP) g_bkt[d.y * CAP + p1] = s.y << 8;
}

// ---------------- dinv + scale layer-1 hw rows by dinv[row] ----------------
__global__ __launch_bounds__(256) void k_dinv_scale() {
    int t = blockIdx.x * blockDim.x + threadIdx.x;
    int gw = t >> 5, lane = t & 31;
    if (gw >= NN) return;
    float di = rsqrtf((float)g_cur[gw] + 1.0f);   // +1 self-loop
    if (lane == 0) g_dinv[gw] = di;
    uint2 u = *(uint2*)&g_hw[gw * CF + lane * 4];
    float2 f0 = __half22float2(*reinterpret_cast<__half2*>(&u.x));
    float2 f1 = __half22float2(*reinterpret_cast<__half2*>(&u.y));
    __half2 p0 = __floats2half2_rn(f0.x * di, f0.y * di);
    __half2 p1 = __floats2half2_rn(f1.x * di, f1.y * di);
    uint2 o;
    o.x = *(uint32_t*)&p0; o.y = *(uint32_t*)&p1;
    *(uint2*)&g_hw[gw * CF + lane * 4] = o;
}

// ---------------- fp16 tensor-core GEMM ------------------------------------
__device__ __forceinline__ void ldsm_x4(uint32_t& r0, uint32_t& r1,
                                        uint32_t& r2, uint32_t& r3, uint32_t a) {
    asm volatile("ldmatrix.sync.aligned.m8n8.x4.shared.b16 {%0,%1,%2,%3}, [%4];"
                 : "=r"(r0), "=r"(r1), "=r"(r2), "=r"(r3) : "r"(a));
}
__device__ __forceinline__ void ldsm_x4_t(uint32_t& r0, uint32_t& r1,
                                          uint32_t& r2, uint32_t& r3, uint32_t a) {
    asm volatile("ldmatrix.sync.aligned.m8n8.x4.trans.shared.b16 {%0,%1,%2,%3}, [%4];"
                 : "=r"(r0), "=r"(r1), "=r"(r2), "=r"(r3) : "r"(a));
}
__device__ __forceinline__ void mma16(float* d, const uint32_t* a,
                                      uint32_t b0, uint32_t b1) {
    asm volatile(
        "mma.sync.aligned.m16n8k16.row.col.f32.f16.f16.f32 "
        "{%0,%1,%2,%3}, {%4,%5,%6,%7}, {%8,%9}, {%0,%1,%2,%3};"
        : "+f"(d[0]), "+f"(d[1]), "+f"(d[2]), "+f"(d[3])
        : "r"(a[0]), "r"(a[1]), "r"(a[2]), "r"(a[3]), "r"(b0), "r"(b1));
}
__device__ __forceinline__ uint2 cvt_hi(float4 v) {
    __half2 h01 = __floats2half2_rn(v.x, v.y);
    __half2 h23 = __floats2half2_rn(v.z, v.w);
    uint2 r;
    r.x = *(uint32_t*)&h01; r.y = *(uint32_t*)&h23;
    return r;
}

// Dynamic smem layout (halves):
//   Ws [128][136]    at 0       (17408)
//   As [2][128][40]  at 17408   (10240)
#define SM_WHI 0
#define SM_AHI 17408
#define SM_TOTAL_HALVES 27648   // 55296 bytes

__global__ __launch_bounds__(256, 2) void k_gemm_tc(const float* __restrict__ Aext,
                                                    const float* __restrict__ W,
                                                    int src_sel, int scale_out) {
    extern __shared__ __half sh[];
    __half* O = g_hw;

    int tid = threadIdx.x;
    int wid = tid >> 5, lane = tid & 31;
    int mrow = (wid >> 1) * 32;
    int ncol0 = (wid & 1) * 64;
    int row0 = blockIdx.x * 128;

    uint32_t sbase = (uint32_t)__cvta_generic_to_shared(sh);
    uint32_t sWhi = sbase + SM_WHI * 2;
    uint32_t sAhi = sbase + SM_AHI * 2;

#pragma unroll
    for (int j = 0; j < 16; j++) {
        int q = tid + j * 256;
        int br = q >> 5, bc = (q & 31) * 4;
        float4 v = *(const float4*)&W[br * CF + bc];
        *(uint2*)&sh[SM_WHI + br * 136 + bc] = cvt_hi(v);
    }
    {
        int row = tid >> 3, cg = tid & 7;
#pragma unroll
        for (int j = 0; j < 4; j++) {
            int r = row + j * 32;
            int gr = row0 + r;
            uint2 hv = make_uint2(0u, 0u);
            if (gr < NN) {
                if (src_sel)
                    hv = *(const uint2*)&g_h1h[gr * CF + cg * 4];
                else
                    hv = cvt_hi(*(const float4*)&Aext[gr * CF + cg * 4]);
            }
            *(uint2*)&sh[SM_AHI + r * 40 + cg * 4] = hv;
        }
    }
    __syncthreads();

    float acc[2][8][4];
#pragma unroll
    for (int mb = 0; mb < 2; mb++)
#pragma unroll
        for (int nt = 0; nt < 8; nt++)
#pragma unroll
            for (int i = 0; i < 4; i++) acc[mb][nt][i] = 0.f;

    int prow = tid >> 3, pcg = tid & 7;
#pragma unroll
    for (int kc = 0; kc < 4; kc++) {
        int buf = kc & 1, nbuf = buf ^ 1;
        uint2 pf[4];
        if (kc < 3) {
#pragma unroll
            for (int j = 0; j < 4; j++) {
                int gr = row0 + prow + j * 32;
                pf[j] = make_uint2(0u, 0u);
                if (gr < NN) {
                    if (src_sel)
                        pf[j] = *(const uint2*)&g_h1h[gr * CF + (kc + 1) * 32 + pcg * 4];
                    else
                        pf[j] = cvt_hi(*(const float4*)&Aext[gr * CF + (kc + 1) * 32 + pcg * 4]);
                }
            }
        }
#pragma unroll
        for (int ks = 0; ks < 2; ks++) {
            int kb = ks * 16;
            uint32_t ah[2][4];
            int arow = mrow + (lane & 15);
            int acol = kb + ((lane & 16) >> 1);
#pragma unroll
            for (int mb = 0; mb < 2; mb++) {
                uint32_t off = (uint32_t)((buf * 5120 + (arow + mb * 16) * 40 + acol) * 2);
                ldsm_x4(ah[mb][0], ah[mb][1], ah[mb][2], ah[mb][3], sAhi + off);
            }
            int krow = kc * 32 + kb + (lane & 7) + (lane & 8);
            int ncol = ncol0 + ((lane & 16) >> 1);
#pragma unroll
            for (int p = 0; p < 4; p++) {
                uint32_t off = (uint32_t)((krow * 136 + ncol + p * 16) * 2);
                uint32_t bh0, bh1, bh2, bh3;
                ldsm_x4_t(bh0, bh1, bh2, bh3, sWhi + off);
#pragma unroll
                for (int mb = 0; mb < 2; mb++) {
                    mma16(acc[mb][2 * p], ah[mb], bh0, bh1);
                    mma16(acc[mb][2 * p + 1], ah[mb], bh2, bh3);
                }
            }
        }
        if (kc < 3) {
#pragma unroll
            for (int j = 0; j < 4; j++) {
                int r = prow + j * 32;
                *(uint2*)&sh[SM_AHI + nbuf * 5120 + r * 40 + pcg * 4] = pf[j];
            }
            __syncthreads();
        }
    }

    int g = lane >> 2, tg = lane & 3;
#pragma unroll
    for (int mb = 0; mb < 2; mb++) {
        int r = row0 + mrow + mb * 16 + g;
        float d0 = 1.f, d1 = 1.f;
        if (scale_out) {
            if (r < NN) d0 = g_dinv[r];
            if (r + 8 < NN) d1 = g_dinv[r + 8];
        }
#pragma unroll
        for (int nt = 0; nt < 8; nt++) {
            int c = ncol0 + nt * 8 + tg * 2;
            if (r < NN)
                *(__half2*)&O[r * CF + c] =
                    __floats2half2_rn(acc[mb][nt][0] * d0, acc[mb][nt][1] * d0);
            if (r + 8 < NN)
                *(__half2*)&O[(r + 8) * CF + c] =
                    __floats2half2_rn(acc[mb][nt][2] * d1, acc[mb][nt][3] * d1);
        }
    }
}

// ---------------- aggregation: 32 lanes/row, byte-offset buckets -----------
#define H2REF(p) (*reinterpret_cast<__half2*>(&(p)))

__global__ __launch_bounds__(256) void k_agg(const float* __restrict__ bias,
                                             int dst_sel /*1=g_h1h 2=g_h2h*/,
                                             int do_relu) {
    int gw = (blockIdx.x * blockDim.x + threadIdx.x) >> 5;
    int lane = threadIdx.x & 31;
    if (gw >= NN) return;
    const char* hwb = (const char*)g_hw + lane * 8;   // per-lane channel base
    const int* bkt = &g_bkt[gw * CAP];

    int cnt = g_cur[gw];
    if (cnt > CAP) cnt = CAP;
    float di = g_dinv[gw];

    // self-loop (hw already scaled by dinv[gw])
    float2 a0, a1;
    {
        uint2 u = *(const uint2*)(hwb + (gw << 8));
        a0 = __half22float2(H2REF(u.x));
        a1 = __half22float2(H2REF(u.y));
    }

    int e = 0;
    for (; e + 7 < cnt; e += 8) {      // 8-edge fp16 tree per flush
        int4 o0 = *(const int4*)&bkt[e];       // warp-uniform broadcasts
        int4 o1 = *(const int4*)&bkt[e + 4];
        uint2 uA = *(const uint2*)(hwb + o0.x);
        uint2 uB = *(const uint2*)(hwb + o0.y);
        uint2 uC = *(const uint2*)(hwb + o0.z);
        uint2 uD = *(const uint2*)(hwb + o0.w);
        uint2 uE = *(const uint2*)(hwb + o1.x);
        uint2 uF = *(const uint2*)(hwb + o1.y);
        uint2 uG = *(const uint2*)(hwb + o1.z);
        uint2 uH = *(const uint2*)(hwb + o1.w);
        __half2 t0 = __hadd2(__hadd2(__hadd2(H2REF(uA.x), H2REF(uB.x)),
                                     __hadd2(H2REF(uC.x), H2REF(uD.x))),
                             __hadd2(__hadd2(H2REF(uE.x), H2REF(uF.x)),
                                     __hadd2(H2REF(uG.x), H2REF(uH.x))));
        __half2 t1 = __hadd2(__hadd2(__hadd2(H2REF(uA.y), H2REF(uB.y)),
                                     __hadd2(H2REF(uC.y), H2REF(uD.y))),
                             __hadd2(__hadd2(H2REF(uE.y), H2REF(uF.y)),
                                     __hadd2(H2REF(uG.y), H2REF(uH.y))));
        float2 f0 = __half22float2(t0);
        float2 f1 = __half22float2(t1);
        a0.x += f0.x; a0.y += f0.y;
        a1.x += f1.x; a1.y += f1.y;
    }
    if (e + 3 < cnt) {                 // 4-edge tree
        int4 o0 = *(const int4*)&bkt[e];
        uint2 uA = *(const uint2*)(hwb + o0.x);
        uint2 uB = *(const uint2*)(hwb + o0.y);
        uint2 uC = *(const uint2*)(hwb + o0.z);
        uint2 uD = *(const uint2*)(hwb + o0.w);
        __half2 t0 = __hadd2(__hadd2(H2REF(uA.x), H2REF(uB.x)),
                             __hadd2(H2REF(uC.x), H2REF(uD.x)));
        __half2 t1 = __hadd2(__hadd2(H2REF(uA.y), H2REF(uB.y)),
                             __hadd2(H2REF(uC.y), H2REF(uD.y)));
        float2 f0 = __half22float2(t0);
        float2 f1 = __half22float2(t1);
        a0.x += f0.x; a0.y += f0.y;
        a1.x += f1.x; a1.y += f1.y;
        e += 4;
    }
    for (; e < cnt; e++) {
        uint2 u = *(const uint2*)(hwb + bkt[e]);
        float2 f0 = __half22float2(H2REF(u.x));
        float2 f1 = __half22float2(H2REF(u.y));
        a0.x += f0.x; a0.y += f0.y;
        a1.x += f1.x; a1.y += f1.y;
    }

    int c4 = lane * 4;
    float4 b = *(const float4*)&bias[c4];
    float r0 = a0.x * di + b.x, r1 = a0.y * di + b.y;
    float r2 = a1.x * di + b.z, r3 = a1.y * di + b.w;
    if (do_relu) {
        r0 = fmaxf(r0, 0.f); r1 = fmaxf(r1, 0.f);
        r2 = fmaxf(r2, 0.f); r3 = fmaxf(r3, 0.f);
    }
    __half2 p0 = __floats2half2_rn(r0, r1);
    __half2 p1 = __floats2half2_rn(r2, r3);
    uint2 u;
    u.x = *(uint32_t*)&p0; u.y = *(uint32_t*)&p1;
    __half* dst = (dst_sel == 1) ? g_h1h : g_h2h;
    *(uint2*)&dst[gw * CF + c4] = u;
}

// ---------------- subgraph mean-pool + classifier; resets cursors ----------
__global__ __launch_bounds__(256) void k_pool(const void* __restrict__ sg,
                                              const float* __restrict__ Wc,
                                              const float* __restrict__ bc,
                                              float* __restrict__ out) {
    __shared__ int s_s64;
    if (threadIdx.x == 0) s_s64 = detect_s64((const unsigned int*)sg);
    __syncthreads();
    int t = blockIdx.x * blockDim.x + threadIdx.x;
    if (t < NN) g_cur[t] = 0;          // reset cursors for the next replay

    int gw = t >> 5;
    int lane = threadIdx.x & 31;
    if (gw >= NS) return;
    int is64 = s_s64;
    int half = lane >> 4, hl = lane & 15;

    float a[8];
#pragma unroll
    for (int i = 0; i < 8; i++) a[i] = 0.f;
    int cnt = 0;
    for (int l = half; l < NL; l += 2) {
        int idx = load_idx(sg, gw * NL + l, is64);
        if (idx >= 0) {
            cnt++;
            uint4 u = *(const uint4*)&g_h2h[idx * CF + hl * 8];
            float2 f0 = __half22float2(H2REF(u.x));
            float2 f1 = __half22float2(H2REF(u.y));
            float2 f2 = __half22float2(H2REF(u.z));
            float2 f3 = __half22float2(H2REF(u.w));
            a[0] += f0.x; a[1] += f0.y; a[2] += f1.x; a[3] += f1.y;
            a[4] += f2.x; a[5] += f2.y; a[6] += f3.x; a[7] += f3.y;
        }
    }
#pragma unroll
    for (int i = 0; i < 8; i++)
        a[i] += __shfl_down_sync(0xffffffffu, a[i], 16);
    cnt += __shfl_down_sync(0xffffffffu, cnt, 16);

    float inv = 1.0f / (float)(cnt > 0 ? cnt : 1);
#pragma unroll
    for (int i = 0; i < 8; i++) a[i] *= inv;

    float res[NCLS];
#pragma unroll
    for (int c = 0; c < NCLS; c++) {
        float v = 0.f;
#pragma unroll
        for (int i = 0; i < 8; i++) v += a[i] * Wc[(hl * 8 + i) * NCLS + c];
        res[c] = v;
    }
#pragma unroll
    for (int c = 0; c < NCLS; c++) {
        float v = res[c];
#pragma unroll
        for (int o = 8; o > 0; o >>= 1) v += __shfl_xor_sync(0xffffffffu, v, o);
        if (lane == 0) out[gw * NCLS + c] = v + bc[c];
    }
}

// ---------------- launch ----------------------------------------------------
extern "C" void kernel_launch(void* const* d_in, const int* in_sizes, int n_in,
                              void* d_out, int out_size) {
    const float* x  = (const float*)d_in[0];   // (N,1,128) contiguous
    const void*  ei = d_in[1];                 // (2,E) int64 or int32
    const void*  sg = d_in[2];                 // (S,64) int64 or int32
    const float* W1 = (const float*)d_in[3];
    const float* b1 = (const float*)d_in[4];
    const float* W2 = (const float*)d_in[5];
    const float* b2 = (const float*)d_in[6];
    const float* Wc = (const float*)d_in[7];
    const float* bc = (const float*)d_in[8];
    float* out = (float*)d_out;

    const int TB = 256;
    const int nbE2 = (NE / 2 + TB - 1) / TB;   // 2 edges / thread
    const int nbG = (NN + 127) / 128;
    const int nbA = (NN * 32 + TB - 1) / TB;   // warp per node
    const int nbP = (NS * 32 + TB - 1) / TB;   // warp per subgraph
    const int GEMM_SMEM = SM_TOTAL_HALVES * 2; // 55296 bytes

    cudaFuncSetAttribute(k_gemm_tc, cudaFuncAttributeMaxDynamicSharedMemorySize,
                         GEMM_SMEM);           // host-side, idempotent, capture-safe

    // Fork: GEMM1 (x,W1 only) on a side stream, overlapping the bucket fill.
    cudaStream_t s2;
    cudaEvent_t evF, evJ;
    cudaStreamCreateWithFlags(&s2, cudaStreamNonBlocking);
    cudaEventCreateWithFlags(&evF, cudaEventDisableTiming);
    cudaEventCreateWithFlags(&evJ, cudaEventDisableTiming);

    cudaEventRecord(evF, 0);
    cudaStreamWaitEvent(s2, evF, 0);

    k_fill<<<nbE2, TB>>>(ei);                  // cursors pre-zeroed (init / k_pool)
    k_gemm_tc<<<nbG, TB, GEMM_SMEM, s2>>>(x, W1, 0, 0);  // hw = x @ W1 (unscaled)
    cudaEventRecord(evJ, s2);
    cudaStreamWaitEvent(0, evJ, 0);            // join: need hw + cursors

    k_dinv_scale<<<nbA, TB>>>();               // dinv + hw *= dinv[row]
    k_agg<<<nbA, TB>>>(b1, 1, 1);              // h1 = relu(di*(sum)+b1)   (f16)
    k_gemm_tc<<<nbG, TB, GEMM_SMEM>>>(x, W2, 1, 1);  // hw = (h1@W2)*dinv[row]
    k_agg<<<nbA, TB>>>(b2, 2, 0);              // h2 = di*(sum)+b2         (f16)
    k_pool<<<nbP, TB>>>(sg, Wc, bc, out);      // + cursor reset
}

// round 16
// speedup vs baseline: 1.0375x; 1.0375x over previous
#include <cuda_runtime.h>
#include <cuda_fp16.h>
#include <cstdint>

#define NN   100000   // nodes
#define CF   128      // feature dim (C_in == H == 128)
#define NE   1600000  // edges
#define NS   4096     // subgraphs
#define NL   64       // max subgraph size
#define NCLS 10
#define CAP  96       // per-node bucket capacity (deg ~ Poisson(16); P(>96)~1e-40)

// ---------------- scratch (no allocations allowed -> __device__ globals) ---
__device__ int    g_cur[NN];        // bucket cursors (zero at load; reset in k_pool)
__device__ float  g_dinv[NN];
__device__ int    g_bkt[NN * CAP];  // per-node buckets: BYTE offsets (src*256)
__device__ __half g_hw[NN * CF];    // h @ W scratch (fp16), pre-scaled by dinv[row]
__device__ __half g_h1h[NN * CF];   // layer-1 output (fp16)
__device__ __half g_h2h[NN * CF];   // layer-2 output (fp16)

// ---------------- dtype detection helpers (per-block, no global state) -----
__device__ __forceinline__ int detect_e64(const unsigned int* ei) {
    for (int i = 0; i < 64; i++)
        if (ei[2 * i + 1] != 0u) return 0;
    return 1;
}
__device__ __forceinline__ int detect_s64(const unsigned int* sg) {
    for (int i = 0; i < 64; i++) {
        unsigned hi = sg[2 * i + 1];
        if (hi != 0u && hi != 0xFFFFFFFFu) return 0;
    }
    return 1;
}
__device__ __forceinline__ int load_idx(const void* p, int i, int is64) {
    return is64 ? (int)((const long long*)p)[i] : ((const int*)p)[i];
}
__device__ __forceinline__ int2 load_pair(const void* p, int base, int i, int is64) {
    if (is64) {
        longlong2 v = ((const longlong2*)((const long long*)p + base))[i];
        return make_int2((int)v.x, (int)v.y);
    }
    return ((const int2*)((const int*)p + base))[i];
}

// ---------------- bucket fill (stores byte offsets src*256) ----------------
__global__ void k_fill(const void* __restrict__ ei) {
    __shared__ int s_e64;
    if (threadIdx.x == 0) s_e64 = detect_e64((const unsigned int*)ei);
    __syncthreads();
    int i = blockIdx.x * blockDim.x + threadIdx.x;
    if (i >= NE / 2) return;
    int2 s = load_pair(ei, 0, i, s_e64);
    int2 d = load_pair(ei, NE, i, s_e64);
    int p0 = atomicAdd(&g_cur[d.x], 1);
    int p1 = atomicAdd(&g_cur[d.y], 1);
    if (p0 < CAP) g_bkt[d.x * CAP + p0] = s.x << 8;   // *CF*sizeof(half)=256
    if (p1 < CAP) g_bkt[d.y * CAP + p1] = s.y << 8;
}

// ---------------- dinv + scale layer-1 hw rows by dinv[row] ----------------
__global__ __launch_bounds__(256) void k_dinv_scale() {
    int t = blockIdx.x * blockDim.x + threadIdx.x;
    int gw = t >> 5, lane = t & 31;
    if (gw >= NN) return;
    float di = rsqrtf((float)g_cur[gw] + 1.0f);   // +1 self-loop
    if (lane == 0) g_dinv[gw] = di;
    uint2 u = *(uint2*)&g_hw[gw * CF + lane * 4];
    float2 f0 = __half22float2(*reinterpret_cast<__half2*>(&u.x));
    float2 f1 = __half22float2(*reinterpret_cast<__half2*>(&u.y));
    __half2 p0 = __floats2half2_rn(f0.x * di, f0.y * di);
    __half2 p1 = __floats2half2_rn(f1.x * di, f1.y * di);
    uint2 o;
    o.x = *(uint32_t*)&p0; o.y = *(uint32_t*)&p1;
    *(uint2*)&g_hw[gw * CF + lane * 4] = o;
}

// ---------------- fp16 tensor-core GEMM ------------------------------------
__device__ __forceinline__ void ldsm_x4(uint32_t& r0, uint32_t& r1,
                                        uint32_t& r2, uint32_t& r3, uint32_t a) {
    asm volatile("ldmatrix.sync.aligned.m8n8.x4.shared.b16 {%0,%1,%2,%3}, [%4];"
                 : "=r"(r0), "=r"(r1), "=r"(r2), "=r"(r3) : "r"(a));
}
__device__ __forceinline__ void ldsm_x4_t(uint32_t& r0, uint32_t& r1,
                                          uint32_t& r2, uint32_t& r3, uint32_t a) {
    asm volatile("ldmatrix.sync.aligned.m8n8.x4.trans.shared.b16 {%0,%1,%2,%3}, [%4];"
                 : "=r"(r0), "=r"(r1), "=r"(r2), "=r"(r3) : "r"(a));
}
__device__ __forceinline__ void mma16(float* d, const uint32_t* a,
                                      uint32_t b0, uint32_t b1) {
    asm volatile(
        "mma.sync.aligned.m16n8k16.row.col.f32.f16.f16.f32 "
        "{%0,%1,%2,%3}, {%4,%5,%6,%7}, {%8,%9}, {%0,%1,%2,%3};"
        : "+f"(d[0]), "+f"(d[1]), "+f"(d[2]), "+f"(d[3])
        : "r"(a[0]), "r"(a[1]), "r"(a[2]), "r"(a[3]), "r"(b0), "r"(b1));
}
__device__ __forceinline__ uint2 cvt_hi(float4 v) {
    __half2 h01 = __floats2half2_rn(v.x, v.y);
    __half2 h23 = __floats2half2_rn(v.z, v.w);
    uint2 r;
    r.x = *(uint32_t*)&h01; r.y = *(uint32_t*)&h23;
    return r;
}

// Dynamic smem layout (halves):
//   Ws [128][136]    at 0       (17408)
//   As [2][128][40]  at 17408   (10240)
#define SM_WHI 0
#define SM_AHI 17408
#define SM_TOTAL_HALVES 27648   // 55296 bytes

__global__ __launch_bounds__(256, 2) void k_gemm_tc(const float* __restrict__ Aext,
                                                    const float* __restrict__ W,
                                                    int src_sel, int scale_out) {
    extern __shared__ __half sh[];
    __half* O = g_hw;

    int tid = threadIdx.x;
    int wid = tid >> 5, lane = tid & 31;
    int mrow = (wid >> 1) * 32;
    int ncol0 = (wid & 1) * 64;
    int row0 = blockIdx.x * 128;

    uint32_t sbase = (uint32_t)__cvta_generic_to_shared(sh);
    uint32_t sWhi = sbase + SM_WHI * 2;
    uint32_t sAhi = sbase + SM_AHI * 2;

#pragma unroll
    for (int j = 0; j < 16; j++) {
        int q = tid + j * 256;
        int br = q >> 5, bc = (q & 31) * 4;
        float4 v = *(const float4*)&W[br * CF + bc];
        *(uint2*)&sh[SM_WHI + br * 136 + bc] = cvt_hi(v);
    }
    {
        int row = tid >> 3, cg = tid & 7;
#pragma unroll
        for (int j = 0; j < 4; j++) {
            int r = row + j * 32;
            int gr = row0 + r;
            uint2 hv = make_uint2(0u, 0u);
            if (gr < NN) {
                if (src_sel)
                    hv = *(const uint2*)&g_h1h[gr * CF + cg * 4];
                else
                    hv = cvt_hi(*(const float4*)&Aext[gr * CF + cg * 4]);
            }
            *(uint2*)&sh[SM_AHI + r * 40 + cg * 4] = hv;
        }
    }
    __syncthreads();

    float acc[2][8][4];
#pragma unroll
    for (int mb = 0; mb < 2; mb++)
#pragma unroll
        for (int nt = 0; nt < 8; nt++)
#pragma unroll
            for (int i = 0; i < 4; i++) acc[mb][nt][i] = 0.f;

    int prow = tid >> 3, pcg = tid & 7;
#pragma unroll
    for (int kc = 0; kc < 4; kc++) {
        int buf = kc & 1, nbuf = buf ^ 1;
        uint2 pf[4];
        if (kc < 3) {
#pragma unroll
            for (int j = 0; j < 4; j++) {
                int gr = row0 + prow + j * 32;
                pf[j] = make_uint2(0u, 0u);
                if (gr < NN) {
                    if (src_sel)
                        pf[j] = *(const uint2*)&g_h1h[gr * CF + (kc + 1) * 32 + pcg * 4];
                    else
                        pf[j] = cvt_hi(*(const float4*)&Aext[gr * CF + (kc + 1) * 32 + pcg * 4]);
                }
            }
        }
#pragma unroll
        for (int ks = 0; ks < 2; ks++) {
            int kb = ks * 16;
            uint32_t ah[2][4];
            int arow = mrow + (lane & 15);
            int acol = kb + ((lane & 16) >> 1);
#pragma unroll
            for (int mb = 0; mb < 2; mb++) {
                uint32_t off = (uint32_t)((buf * 5120 + (arow + mb * 16) * 40 + acol) * 2);
                ldsm_x4(ah[mb][0], ah[mb][1], ah[mb][2], ah[mb][3], sAhi + off);
            }
            int krow = kc * 32 + kb + (lane & 7) + (lane & 8);
            int ncol = ncol0 + ((lane & 16) >> 1);
#pragma unroll
            for (int p = 0; p < 4; p++) {
                uint32_t off = (uint32_t)((krow * 136 + ncol + p * 16) * 2);
                uint32_t bh0, bh1, bh2, bh3;
                ldsm_x4_t(bh0, bh1, bh2, bh3, sWhi + off);
#pragma unroll
                for (int mb = 0; mb < 2; mb++) {
                    mma16(acc[mb][2 * p], ah[mb], bh0, bh1);
                    mma16(acc[mb][2 * p + 1], ah[mb], bh2, bh3);
                }
            }
        }
        if (kc < 3) {
#pragma unroll
            for (int j = 0; j < 4; j++) {
                int r = prow + j * 32;
                *(uint2*)&sh[SM_AHI + nbuf * 5120 + r * 40 + pcg * 4] = pf[j];
            }
            __syncthreads();
        }
    }

    int g = lane >> 2, tg = lane & 3;
#pragma unroll
    for (int mb = 0; mb < 2; mb++) {
        int r = row0 + mrow + mb * 16 + g;
        float d0 = 1.f, d1 = 1.f;
        if (scale_out) {
            if (r < NN) d0 = g_dinv[r];
            if (r + 8 < NN) d1 = g_dinv[r + 8];
        }
#pragma unroll
        for (int nt = 0; nt < 8; nt++) {
            int c = ncol0 + nt * 8 + tg * 2;
            if (r < NN)
                *(__half2*)&O[r * CF + c] =
                    __floats2half2_rn(acc[mb][nt][0] * d0, acc[mb][nt][1] * d0);
            if (r + 8 < NN)
                *(__half2*)&O[(r + 8) * CF + c] =
                    __floats2half2_rn(acc[mb][nt][2] * d1, acc[mb][nt][3] * d1);
        }
    }
}

// ---------------- aggregation: 32 lanes/row, 4-edge tree, byte offsets -----
#define H2REF(p) (*reinterpret_cast<__half2*>(&(p)))

__global__ __launch_bounds__(256) void k_agg(const float* __restrict__ bias,
                                             int dst_sel /*1=g_h1h 2=g_h2h*/,
                                             int do_relu) {
    int gw = (blockIdx.x * blockDim.x + threadIdx.x) >> 5;
    int lane = threadIdx.x & 31;
    if (gw >= NN) return;
    const char* hwb = (const char*)g_hw + lane * 8;   // per-lane channel base
    const int* bkt = &g_bkt[gw * CAP];

    int cnt = g_cur[gw];
    if (cnt > CAP) cnt = CAP;
    float di = g_dinv[gw];

    // self-loop (hw already scaled by dinv[gw])
    float2 a0, a1;
    {
        uint2 u = *(const uint2*)(hwb + (gw << 8));
        a0 = __half22float2(H2REF(u.x));
        a1 = __half22float2(H2REF(u.y));
    }

    int e = 0;
    for (; e + 3 < cnt; e += 4) {      // 4-edge fp16 tree per flush
        int4 o0 = *(const int4*)&bkt[e];       // warp-uniform broadcast
        uint2 uA = *(const uint2*)(hwb + o0.x);
        uint2 uB = *(const uint2*)(hwb + o0.y);
        uint2 uC = *(const uint2*)(hwb + o0.z);
        uint2 uD = *(const uint2*)(hwb + o0.w);
        __half2 t0 = __hadd2(__hadd2(H2REF(uA.x), H2REF(uB.x)),
                             __hadd2(H2REF(uC.x), H2REF(uD.x)));
        __half2 t1 = __hadd2(__hadd2(H2REF(uA.y), H2REF(uB.y)),
                             __hadd2(H2REF(uC.y), H2REF(uD.y)));
        float2 f0 = __half22float2(t0);
        float2 f1 = __half22float2(t1);
        a0.x += f0.x; a0.y += f0.y;
        a1.x += f1.x; a1.y += f1.y;
    }
    for (; e < cnt; e++) {
        uint2 u = *(const uint2*)(hwb + bkt[e]);
        float2 f0 = __half22float2(H2REF(u.x));
        float2 f1 = __half22float2(H2REF(u.y));
        a0.x += f0.x; a0.y += f0.y;
        a1.x += f1.x; a1.y += f1.y;
    }

    int c4 = lane * 4;
    float4 b = *(const float4*)&bias[c4];
    float r0 = a0.x * di + b.x, r1 = a0.y * di + b.y;
    float r2 = a1.x * di + b.z, r3 = a1.y * di + b.w;
    if (do_relu) {
        r0 = fmaxf(r0, 0.f); r1 = fmaxf(r1, 0.f);
        r2 = fmaxf(r2, 0.f); r3 = fmaxf(r3, 0.f);
    }
    __half2 p0 = __floats2half2_rn(r0, r1);
    __half2 p1 = __floats2half2_rn(r2, r3);
    uint2 u;
    u.x = *(uint32_t*)&p0; u.y = *(uint32_t*)&p1;
    __half* dst = (dst_sel == 1) ? g_h1h : g_h2h;
    *(uint2*)&dst[gw * CF + c4] = u;
}

// ---------------- subgraph mean-pool + classifier; resets cursors ----------
__global__ __launch_bounds__(256) void k_pool(const void* __restrict__ sg,
                                              const float* __restrict__ Wc,
                                              const float* __restrict__ bc,
                                              float* __restrict__ out) {
    __shared__ int s_s64;
    if (threadIdx.x == 0) s_s64 = detect_s64((const unsigned int*)sg);
    __syncthreads();
    int t = blockIdx.x * blockDim.x + threadIdx.x;
    if (t < NN) g_cur[t] = 0;          // reset cursors for the next replay

    int gw = t >> 5;
    int lane = threadIdx.x & 31;
    if (gw >= NS) return;
    int is64 = s_s64;
    int half = lane >> 4, hl = lane & 15;

    float a[8];
#pragma unroll
    for (int i = 0; i < 8; i++) a[i] = 0.f;
    int cnt = 0;
    for (int l = half; l < NL; l += 2) {
        int idx = load_idx(sg, gw * NL + l, is64);
        if (idx >= 0) {
            cnt++;
            uint4 u = *(const uint4*)&g_h2h[idx * CF + hl * 8];
            float2 f0 = __half22float2(H2REF(u.x));
            float2 f1 = __half22float2(H2REF(u.y));
            float2 f2 = __half22float2(H2REF(u.z));
            float2 f3 = __half22float2(H2REF(u.w));
            a[0] += f0.x; a[1] += f0.y; a[2] += f1.x; a[3] += f1.y;
            a[4] += f2.x; a[5] += f2.y; a[6] += f3.x; a[7] += f3.y;
        }
    }
#pragma unroll
    for (int i = 0; i < 8; i++)
        a[i] += __shfl_down_sync(0xffffffffu, a[i], 16);
    cnt += __shfl_down_sync(0xffffffffu, cnt, 16);

    float inv = 1.0f / (float)(cnt > 0 ? cnt : 1);
#pragma unroll
    for (int i = 0; i < 8; i++) a[i] *= inv;

    float res[NCLS];
#pragma unroll
    for (int c = 0; c < NCLS; c++) {
        float v = 0.f;
#pragma unroll
        for (int i = 0; i < 8; i++) v += a[i] * Wc[(hl * 8 + i) * NCLS + c];
        res[c] = v;
    }
#pragma unroll
    for (int c = 0; c < NCLS; c++) {
        float v = res[c];
#pragma unroll
        for (int o = 8; o > 0; o >>= 1) v += __shfl_xor_sync(0xffffffffu, v, o);
        if (lane == 0) out[gw * NCLS + c] = v + bc[c];
    }
}

// ---------------- launch ----------------------------------------------------
extern "C" void kernel_launch(void* const* d_in, const int* in_sizes, int n_in,
                              void* d_out, int out_size) {
    const float* x  = (const float*)d_in[0];   // (N,1,128) contiguous
    const void*  ei = d_in[1];                 // (2,E) int64 or int32
    const void*  sg = d_in[2];                 // (S,64) int64 or int32
    const float* W1 = (const float*)d_in[3];
    const float* b1 = (const float*)d_in[4];
    const float* W2 = (const float*)d_in[5];
    const float* b2 = (const float*)d_in[6];
    const float* Wc = (const float*)d_in[7];
    const float* bc = (const float*)d_in[8];
    float* out = (float*)d_out;

    const int TB = 256;
    const int nbE2 = (NE / 2 + TB - 1) / TB;   // 2 edges / thread
    const int nbG = (NN + 127) / 128;
    const int nbA = (NN * 32 + TB - 1) / TB;   // warp per node
    const int nbP = (NS * 32 + TB - 1) / TB;   // warp per subgraph
    const int GEMM_SMEM = SM_TOTAL_HALVES * 2; // 55296 bytes

    cudaFuncSetAttribute(k_gemm_tc, cudaFuncAttributeMaxDynamicSharedMemorySize,
                         GEMM_SMEM);           // host-side, idempotent, capture-safe

    // Fork: GEMM1 (x,W1 only) on a side stream, overlapping the bucket fill.
    cudaStream_t s2;
    cudaEvent_t evF, evJ;
    cudaStreamCreateWithFlags(&s2, cudaStreamNonBlocking);
    cudaEventCreateWithFlags(&evF, cudaEventDisableTiming);
    cudaEventCreateWithFlags(&evJ, cudaEventDisableTiming);

    cudaEventRecord(evF, 0);
    cudaStreamWaitEvent(s2, evF, 0);

    k_fill<<<nbE2, TB>>>(ei);                  // cursors pre-zeroed (init / k_pool)
    k_gemm_tc<<<nbG, TB, GEMM_SMEM, s2>>>(x, W1, 0, 0);  // hw = x @ W1 (unscaled)
    cudaEventRecord(evJ, s2);
    cudaStreamWaitEvent(0, evJ, 0);            // join: need hw + cursors

    k_dinv_scale<<<nbA, TB>>>();               // dinv + hw *= dinv[row]
    k_agg<<<nbA, TB>>>(b1, 1, 1);              // h1 = relu(di*(sum)+b1)   (f16)
    k_gemm_tc<<<nbG, TB, GEMM_SMEM>>>(x, W2, 1, 1);  // hw = (h1@W2)*dinv[row]
    k_agg<<<nbA, TB>>>(b2, 2, 0);              // h2 = di*(sum)+b2         (f16)
    k_pool<<<nbP, TB>>>(sg, Wc, bc, out);      // + cursor reset
}